// round 15
// baseline (speedup 1.0000x reference)
#include <cuda_runtime.h>
#include <cuda_bf16.h>
#include <math.h>
#include <stdint.h>

#define D_MODEL 1024
#define D_STATE 16
#define D_CONV  4
#define D_INNER 2048
#define DT_RANK 64
#define NBLK    4
#define BATCH   2
#define SEQLEN  1024
#define M_TOK   (BATCH*SEQLEN)   // 2048 tokens
#define XD      96               // dt_rank + 2*d_state

// weight layout inside the big split buffers (elems, per layer)
#define WL_IN   (2*D_INNER*D_MODEL)   // 4,194,304
#define WL_XP   (128*D_INNER)         //   262,144 (96 rows padded to 128)
#define WL_DT   (D_INNER*DT_RANK)     //   131,072
#define WL_OUT  (D_MODEL*D_INNER)     // 2,097,152
#define OFF_XP  WL_IN
#define OFF_DT  (WL_IN + WL_XP)
#define OFF_OUT (WL_IN + WL_XP + WL_DT)
#define WPL     (WL_IN + WL_XP + WL_DT + WL_OUT)   // 6,684,672
#define WTOT    ((size_t)NBLK * WPL)               // 26,738,688

// ---------------- scratch (no allocation allowed) ----------------
__device__ __align__(256) float g_xz[(size_t)M_TOK*2*D_INNER];
__device__ __align__(256) float g_u[(size_t)M_TOK*D_INNER];
__device__ __align__(256) float g_xdbl[M_TOK*XD];
__device__ __align__(256) float g_part[(size_t)8*M_TOK*128];
__device__ __align__(256) float g_dt[(size_t)M_TOK*D_INNER];
// bf16 split activation buffers (hi/lo)
__device__ __align__(256) __nv_bfloat16 g_A0[(size_t)M_TOK*D_INNER];
__device__ __align__(256) __nv_bfloat16 g_A1[(size_t)M_TOK*D_INNER];
__device__ __align__(256) __nv_bfloat16 g_H0[(size_t)M_TOK*D_MODEL];
__device__ __align__(256) __nv_bfloat16 g_H1[(size_t)M_TOK*D_MODEL];
// bf16 split weight buffers: ALL layers, ALL weight types
__device__ __align__(256) __nv_bfloat16 g_W0[WTOT];
__device__ __align__(256) __nv_bfloat16 g_W1[WTOT];

__device__ __forceinline__ float siluf(float v) {
    return v / (1.f + __expf(-v));
}

__device__ __forceinline__ uint32_t smem_u32(const void* p) {
    uint32_t a;
    asm("{ .reg .u64 t; cvta.to.shared.u64 t, %1; cvt.u32.u64 %0, t; }" : "=r"(a) : "l"(p));
    return a;
}
#define SWZ128(o) ((o) ^ (((o) >> 3) & 0x70))

// ---- cp.async helpers ----
__device__ __forceinline__ void cp16(uint32_t saddr, const void* gaddr) {
    asm volatile("cp.async.cg.shared.global [%0], [%1], 16;" :: "r"(saddr), "l"(gaddr));
}
__device__ __forceinline__ void cp_commit() { asm volatile("cp.async.commit_group;"); }
template<int N> __device__ __forceinline__ void cp_wait() {
    asm volatile("cp.async.wait_group %0;" :: "n"(N));
}

// ---- ldmatrix + mma.sync ----
__device__ __forceinline__ void ldm_x4(uint32_t addr, uint32_t f[4]) {
    asm volatile("ldmatrix.sync.aligned.m8n8.x4.shared.b16 {%0,%1,%2,%3}, [%4];"
                 : "=r"(f[0]), "=r"(f[1]), "=r"(f[2]), "=r"(f[3]) : "r"(addr));
}
__device__ __forceinline__ void mma16816(float c[4], const uint32_t a[4],
                                         uint32_t b0, uint32_t b1) {
    asm volatile(
        "mma.sync.aligned.m16n8k16.row.col.f32.bf16.bf16.f32 "
        "{%0,%1,%2,%3}, {%4,%5,%6,%7}, {%8,%9}, {%0,%1,%2,%3};"
        : "+f"(c[0]), "+f"(c[1]), "+f"(c[2]), "+f"(c[3])
        : "r"(a[0]), "r"(a[1]), "r"(a[2]), "r"(a[3]), "r"(b0), "r"(b1));
}

// ================= bf16x2-split HMMA GEMM =================
//  C[M,N] = (A0+A1)[M,K] * (W0+W1)[N,K]^T, 3-term split, fp32 accum.
//  BM=BN=128, BK=64, 256 threads (8 warps: 4M x 2N), 3-stage cp.async ring.
//  Inner loop issues MMAs grouped BY TERM so consecutive HMMAs never share an
//  accumulator (16 distinct accs between reuses -> no RAW stalls).
//  EPI: 0 none, 1 softplus(x+bias[n]), 2 silu
//  OSPLIT: write hi/lo bf16 outputs instead of fp32
//  SPLITK: grid.z K-splits of size ksplit, fp32 partials at z*M*N
#define GSM_STAGE 65536            // 4 sub-tiles x 128x64 bf16 (16KB each)
#define GSM_TOTAL (3*GSM_STAGE)

template<int EPI, int OSPLIT, int SPLITK>
__global__ void __launch_bounds__(256, 1) mmagemm_k(
    const __nv_bfloat16* __restrict__ A0, const __nv_bfloat16* __restrict__ A1,
    const __nv_bfloat16* __restrict__ W0, const __nv_bfloat16* __restrict__ W1,
    const float* __restrict__ bias, float* __restrict__ C,
    __nv_bfloat16* __restrict__ Chi, __nv_bfloat16* __restrict__ Clo,
    int M, int N, int K, int ksplit)
{
    extern __shared__ char dsm[];
    const uint32_t sb = smem_u32(dsm);
    const int tid  = threadIdx.x;
    const int wid  = tid >> 5;
    const int lane = tid & 31;
    const int wm = wid & 3;
    const int wn = wid >> 2;
    const int bm = blockIdx.y * 128;
    const int bn = blockIdx.x * 128;

    int kbase = 0, Kloc = K;
    if (SPLITK) {
        kbase = blockIdx.z * ksplit;
        Kloc  = ksplit;
        C += (size_t)blockIdx.z * (size_t)M * N;
    }

    const __nv_bfloat16* gb[4] = {
        A0 + (size_t)bm * K + kbase, A1 + (size_t)bm * K + kbase,
        W0 + (size_t)bn * K + kbase, W1 + (size_t)bn * K + kbase };

    const int ch = tid & 7;          // 16B chunk in 128B row
    const int r0 = tid >> 3;         // 0..31

    // issue one of the 4 sub-tiles (A0/A1/W0/W1) of a chunk
    auto issue_quarter = [&](int kt, int stage, int buf) {
        uint32_t st = sb + stage * GSM_STAGE + buf * 16384;
        const __nv_bfloat16* g = gb[buf] + kt + ch * 8;
#pragma unroll
        for (int j = 0; j < 4; j++) {
            int row = r0 + j * 32;
            uint32_t o = (uint32_t)(row * 128 + ch * 16);
            cp16(st + SWZ128(o), g + (size_t)row * K);
        }
    };

    float acc[2][8][4];
#pragma unroll
    for (int i = 0; i < 2; i++)
#pragma unroll
        for (int j = 0; j < 8; j++)
#pragma unroll
            for (int q = 0; q < 4; q++) acc[i][j][q] = 0.f;

    const int a_row = lane & 15;
    const int a_kof = (lane >> 4) << 3;
    const int b_row = (lane & 7) + ((lane & 16) ? 8 : 0);
    const int b_kof = (lane & 8) ? 8 : 0;

    const int T = Kloc / 64;
    // prologue: 2 chunks in flight
#pragma unroll
    for (int b = 0; b < 4; b++) issue_quarter(0, 0, b);
    cp_commit();
    if (T > 1) {
#pragma unroll
        for (int b = 0; b < 4; b++) issue_quarter(64, 1, b);
        cp_commit();
    }

    for (int t = 0; t < T; t++) {
        if (t + 1 < T) cp_wait<1>();   // chunk t complete, t+1 still loading
        else           cp_wait<0>();   // tail: everything complete
        __syncthreads();               // chunk t visible; iter t-1 reads done

        const int s = t % 3;
        const uint32_t stA0 = sb + s * GSM_STAGE;
        const uint32_t stA1 = stA0 + 16384;
        const uint32_t stW0 = stA0 + 32768;
        const uint32_t stW1 = stA0 + 49152;

        const bool pf = (t + 2 < T);
        const int  ps = (t + 2) % 3;

#pragma unroll
        for (int kk = 0; kk < 4; kk++) {
            if (pf) issue_quarter((t + 2) * 64, ps, kk);   // spread loads over compute
            const int k0 = kk * 16;

            // ---- load ALL fragments for this k16 step ----
            uint32_t a0f[2][4], a1f[2][4];
#pragma unroll
            for (int mt = 0; mt < 2; mt++) {
                int row = wm * 32 + mt * 16 + a_row;
                uint32_t o = (uint32_t)(row * 128 + (k0 + a_kof) * 2);
                ldm_x4(stA0 + SWZ128(o), a0f[mt]);
                ldm_x4(stA1 + SWZ128(o), a1f[mt]);
            }
            uint32_t w0f[4][4], w1f[4][4];
#pragma unroll
            for (int nq = 0; nq < 4; nq++) {
                int nrow = wn * 64 + nq * 16 + b_row;
                uint32_t o = (uint32_t)(nrow * 128 + (k0 + b_kof) * 2);
                ldm_x4(stW0 + SWZ128(o), w0f[nq]);
                ldm_x4(stW1 + SWZ128(o), w1f[nq]);
            }

            // ---- issue MMAs grouped by term: no consecutive acc reuse ----
#pragma unroll
            for (int nq = 0; nq < 4; nq++)
#pragma unroll
                for (int mt = 0; mt < 2; mt++)
#pragma unroll
                    for (int h = 0; h < 2; h++)
                        mma16816(acc[mt][nq*2+h], a0f[mt], w0f[nq][2*h], w0f[nq][2*h+1]);
#pragma unroll
            for (int nq = 0; nq < 4; nq++)
#pragma unroll
                for (int mt = 0; mt < 2; mt++)
#pragma unroll
                    for (int h = 0; h < 2; h++)
                        mma16816(acc[mt][nq*2+h], a0f[mt], w1f[nq][2*h], w1f[nq][2*h+1]);
#pragma unroll
            for (int nq = 0; nq < 4; nq++)
#pragma unroll
                for (int mt = 0; mt < 2; mt++)
#pragma unroll
                    for (int h = 0; h < 2; h++)
                        mma16816(acc[mt][nq*2+h], a1f[mt], w0f[nq][2*h], w0f[nq][2*h+1]);
        }
        if (pf) cp_commit();
    }

    // ---- epilogue ----
    const int erow = lane >> 2;
    const int ecol = (lane & 3) * 2;
#pragma unroll
    for (int mt = 0; mt < 2; mt++) {
#pragma unroll
        for (int nt = 0; nt < 8; nt++) {
            int n = bn + wn * 64 + nt * 8 + ecol;
#pragma unroll
            for (int h = 0; h < 2; h++) {
                int m = bm + wm * 32 + mt * 16 + erow + h * 8;
                float vx = acc[mt][nt][2*h], vy = acc[mt][nt][2*h+1];
                if (EPI == 1) {
                    vx += bias[n]; vy += bias[n+1];
                    vx = fmaxf(vx, 0.f) + log1pf(__expf(-fabsf(vx)));
                    vy = fmaxf(vy, 0.f) + log1pf(__expf(-fabsf(vy)));
                }
                if (EPI == 2) { vx = siluf(vx); vy = siluf(vy); }
                if (OSPLIT) {
                    __nv_bfloat16 hx = __float2bfloat16(vx);
                    __nv_bfloat16 hy = __float2bfloat16(vy);
                    __nv_bfloat162 hp; hp.x = hx; hp.y = hy;
                    __nv_bfloat162 lp;
                    lp.x = __float2bfloat16(vx - __bfloat162float(hx));
                    lp.y = __float2bfloat16(vy - __bfloat162float(hy));
                    *reinterpret_cast<__nv_bfloat162*>(Chi + (size_t)m * N + n) = hp;
                    *reinterpret_cast<__nv_bfloat162*>(Clo + (size_t)m * N + n) = lp;
                } else {
                    float2 v = {vx, vy};
                    *reinterpret_cast<float2*>(C + (size_t)m * N + n) = v;
                }
            }
        }
    }
}

// ======== mega weight cvt: all layers, all types, one launch ========
__global__ void cvt_all_k(const float* __restrict__ inw, const float* __restrict__ xpw,
                          const float* __restrict__ dtw, const float* __restrict__ outw,
                          __nv_bfloat16* __restrict__ hi, __nv_bfloat16* __restrict__ lo)
{
    size_t i = (size_t)blockIdx.x * blockDim.x + threadIdx.x;   // < WTOT
    int layer = (int)(i / WPL);
    int r = (int)(i - (size_t)layer * WPL);
    float v;
    if (r < WL_IN) {
        v = inw[(size_t)layer * WL_IN + r];
    } else if (r < OFF_DT) {
        int rr = r - OFF_XP;
        int row = rr / D_INNER, col = rr - row * D_INNER;
        v = (row < XD) ? xpw[(size_t)layer * XD * D_INNER + (size_t)row * D_INNER + col] : 0.f;
    } else if (r < OFF_OUT) {
        v = dtw[(size_t)layer * WL_DT + (r - OFF_DT)];
    } else {
        v = outw[(size_t)layer * WL_OUT + (r - OFF_OUT)];
    }
    __nv_bfloat16 h = __float2bfloat16(v);
    hi[i] = h;
    lo[i] = __float2bfloat16(v - __bfloat162float(h));
}

// ================= embedding (writes split directly) =================
__global__ void embed_split_k(const float* __restrict__ x, const float* __restrict__ ew,
                              const float* __restrict__ eb,
                              __nv_bfloat16* __restrict__ hi,
                              __nv_bfloat16* __restrict__ lo)
{
    int i = blockIdx.x * blockDim.x + threadIdx.x;
    int d = i % D_MODEL, m = i / D_MODEL;
    float v = fmaf(x[m], ew[d], eb[d]);
    __nv_bfloat16 h = __float2bfloat16(v);
    hi[i] = h;
    lo[i] = __float2bfloat16(v - __bfloat162float(h));
}

// ============ causal depthwise conv + silu (fp32 + split outputs) ============
__global__ void conv_silu_k(const float* __restrict__ xz, const float* __restrict__ cw,
                            const float* __restrict__ cb, float* __restrict__ u,
                            __nv_bfloat16* __restrict__ uhi, __nv_bfloat16* __restrict__ ulo)
{
    int i = blockIdx.x * blockDim.x + threadIdx.x;
    int d = i % D_INNER;
    int m = i / D_INNER;
    int t = m % SEQLEN;
    float acc = cb[d];
#pragma unroll
    for (int k = 0; k < D_CONV; k++) {
        int tt = t - (D_CONV-1) + k;
        if (tt >= 0)
            acc = fmaf(cw[d*D_CONV + k], xz[(size_t)(m-(D_CONV-1)+k)*(2*D_INNER) + d], acc);
    }
    float v = siluf(acc);
    u[i] = v;
    __nv_bfloat16 h = __float2bfloat16(v);
    uhi[i] = h;
    ulo[i] = __float2bfloat16(v - __bfloat162float(h));
}

// ======= reduce 8 split-K partials -> xdbl fp32 + dt_lo bf16 split =======
__global__ void reduce8_k(const float* __restrict__ part,
                          float* __restrict__ xdbl,
                          __nv_bfloat16* __restrict__ dh, __nv_bfloat16* __restrict__ dl)
{
    int i = blockIdx.x * blockDim.x + threadIdx.x;   // M_TOK*96
    if (i < M_TOK * XD) {
        int m = i / XD, c = i - m * XD;
        float s = 0.f;
#pragma unroll
        for (int z = 0; z < 8; z++)
            s += part[(size_t)z * M_TOK * 128 + (size_t)m * 128 + c];
        xdbl[i] = s;
        if (c < DT_RANK) {
            __nv_bfloat16 h = __float2bfloat16(s);
            dh[(size_t)m * DT_RANK + c] = h;
            dl[(size_t)m * DT_RANK + c] = __float2bfloat16(s - __bfloat162float(h));
        }
    }
}

// ---------------- selective scan + gating fused (writes yg split) ----------------
#define SC_D 32
#define SC_T 64
__global__ void __launch_bounds__(512) scan_k(
    const float* __restrict__ dt, const float* __restrict__ u,
    const float* __restrict__ xdbl, const float* __restrict__ xz,
    const float* __restrict__ A_log, const float* __restrict__ Dp,
    __nv_bfloat16* __restrict__ yhi, __nv_bfloat16* __restrict__ ylo)
{
    __shared__ float s_dt[SC_T][SC_D];
    __shared__ float s_u [SC_T][SC_D];
    __shared__ float s_z [SC_T][SC_D];
    __shared__ float s_B [SC_T][D_STATE];
    __shared__ float s_C [SC_T][D_STATE];

    const int b  = blockIdx.y;
    const int d0 = blockIdx.x * SC_D;
    const int tid = threadIdx.x;
    const int n  = tid & 15;
    const int dl = tid >> 4;
    const int d  = d0 + dl;

    const float Aval = -__expf(A_log[d*D_STATE + n]);
    const float Dval = Dp[d];
    float s = 0.f;
    const size_t rowbase = (size_t)b * SEQLEN;

    for (int t0 = 0; t0 < SEQLEN; t0 += SC_T) {
        for (int idx = tid; idx < SC_T*SC_D; idx += 512) {
            int tl = idx / SC_D, dd = idx % SC_D;
            size_t r = rowbase + t0 + tl;
            s_dt[tl][dd] = dt[r*D_INNER + d0 + dd];
            s_u [tl][dd] = u [r*D_INNER + d0 + dd];
            s_z [tl][dd] = xz[r*(2*D_INNER) + D_INNER + d0 + dd];
        }
        for (int idx = tid; idx < SC_T*D_STATE; idx += 512) {
            int tl = idx / D_STATE, nn = idx % D_STATE;
            size_t r = rowbase + t0 + tl;
            s_B[tl][nn] = xdbl[r*XD + DT_RANK + nn];
            s_C[tl][nn] = xdbl[r*XD + DT_RANK + D_STATE + nn];
        }
        __syncthreads();

        for (int tl = 0; tl < SC_T; tl++) {
            float dtv = s_dt[tl][dl];
            float uv  = s_u [tl][dl];
            float dA  = __expf(dtv * Aval);
            s = fmaf(dA, s, dtv * uv * s_B[tl][n]);
            float y = s * s_C[tl][n];
#pragma unroll
            for (int off = 8; off; off >>= 1)
                y += __shfl_xor_sync(0xffffffffu, y, off, 16);
            if (n == 0) {
                float zv = s_z[tl][dl];
                float v  = fmaf(Dval, uv, y) * siluf(zv);
                __nv_bfloat16 h = __float2bfloat16(v);
                size_t o = (rowbase + t0 + tl)*D_INNER + d;
                yhi[o] = h;
                ylo[o] = __float2bfloat16(v - __bfloat162float(h));
            }
        }
        __syncthreads();
    }
}

// ---------------- host ----------------
extern "C" void kernel_launch(void* const* d_in, const int* in_sizes, int n_in,
                              void* d_out, int out_size)
{
    const float* x          = (const float*)d_in[0];
    const float* emb_w      = (const float*)d_in[1];
    const float* emb_b      = (const float*)d_in[2];
    const float* in_proj_w  = (const float*)d_in[3];
    const float* conv_w     = (const float*)d_in[4];
    const float* conv_b     = (const float*)d_in[5];
    const float* x_proj_w   = (const float*)d_in[6];
    const float* dt_proj_w  = (const float*)d_in[7];
    const float* dt_proj_b  = (const float*)d_in[8];
    const float* A_log      = (const float*)d_in[9];
    const float* D_param    = (const float*)d_in[10];
    const float* out_proj_w = (const float*)d_in[11];
    float* out = (float*)d_out;

    float *pxz, *pu, *pxdbl, *ppart, *pdt;
    __nv_bfloat16 *pA0, *pA1, *pH0, *pH1, *pW0, *pW1;
    cudaGetSymbolAddress((void**)&pxz,   g_xz);
    cudaGetSymbolAddress((void**)&pu,    g_u);
    cudaGetSymbolAddress((void**)&pxdbl, g_xdbl);
    cudaGetSymbolAddress((void**)&ppart, g_part);
    cudaGetSymbolAddress((void**)&pdt,   g_dt);
    cudaGetSymbolAddress((void**)&pA0,   g_A0);
    cudaGetSymbolAddress((void**)&pA1,   g_A1);
    cudaGetSymbolAddress((void**)&pH0,   g_H0);
    cudaGetSymbolAddress((void**)&pH1,   g_H1);
    cudaGetSymbolAddress((void**)&pW0,   g_W0);
    cudaGetSymbolAddress((void**)&pW1,   g_W1);

    cudaFuncSetAttribute(mmagemm_k<0,0,0>, cudaFuncAttributeMaxDynamicSharedMemorySize, GSM_TOTAL);
    cudaFuncSetAttribute(mmagemm_k<0,0,1>, cudaFuncAttributeMaxDynamicSharedMemorySize, GSM_TOTAL);
    cudaFuncSetAttribute(mmagemm_k<1,0,0>, cudaFuncAttributeMaxDynamicSharedMemorySize, GSM_TOTAL);
    cudaFuncSetAttribute(mmagemm_k<2,1,0>, cudaFuncAttributeMaxDynamicSharedMemorySize, GSM_TOTAL);
    cudaFuncSetAttribute(mmagemm_k<2,0,0>, cudaFuncAttributeMaxDynamicSharedMemorySize, GSM_TOTAL);

    // all weight conversions in one launch (WTOT divisible by 256)
    cvt_all_k<<<(unsigned)(WTOT/256), 256>>>(in_proj_w, x_proj_w, dt_proj_w, out_proj_w, pW0, pW1);

    embed_split_k<<<(M_TOK*D_MODEL)/256, 256>>>(x, emb_w, emb_b, pH0, pH1);

    for (int i = 0; i < NBLK; i++) {
        const __nv_bfloat16* w0 = pW0 + (size_t)i * WPL;
        const __nv_bfloat16* w1 = pW1 + (size_t)i * WPL;

        // --- GEMM1 (HMMA): xz = h @ in_proj_w^T  [2048 x 4096 x 1024]
        mmagemm_k<0,0,0><<<dim3((2*D_INNER)/128, M_TOK/128), 256, GSM_TOTAL>>>(
            pH0, pH1, w0, w1, nullptr, pxz, nullptr, nullptr,
            M_TOK, 2*D_INNER, D_MODEL, 0);

        // --- depthwise conv + silu -> u (fp32 + split)
        conv_silu_k<<<(M_TOK*D_INNER)/256, 256>>>(
            pxz, conv_w + (size_t)i*D_INNER*D_CONV, conv_b + (size_t)i*D_INNER,
            pu, pA0, pA1);

        // --- GEMM2 (HMMA split-K x8): x_dbl = u @ x_proj_w^T  [2048 x 96(pad128) x 2048]
        mmagemm_k<0,0,1><<<dim3(1, M_TOK/128, 8), 256, GSM_TOTAL>>>(
            pA0, pA1, w0 + OFF_XP, w1 + OFF_XP, nullptr, ppart, nullptr, nullptr,
            M_TOK, 128, D_INNER, D_INNER/8);
        reduce8_k<<<(M_TOK*XD + 255)/256, 256>>>(ppart, pxdbl, pA0, pA1);

        // --- GEMM3 (HMMA): dt = softplus(dt_lo @ dt_proj_w^T + b)  [2048 x 2048 x 64]
        mmagemm_k<1,0,0><<<dim3(D_INNER/128, M_TOK/128), 256, GSM_TOTAL>>>(
            pA0, pA1, w0 + OFF_DT, w1 + OFF_DT, dt_proj_b + (size_t)i*D_INNER,
            pdt, nullptr, nullptr, M_TOK, D_INNER, DT_RANK, 0);

        // --- selective scan + gating -> yg split
        scan_k<<<dim3(D_INNER/SC_D, BATCH), 512>>>(
            pdt, pu, pxdbl, pxz,
            A_log + (size_t)i*D_INNER*D_STATE, D_param + (size_t)i*D_INNER, pA0, pA1);

        // --- GEMM4 (HMMA): h' = silu(yg @ out_proj_w^T)  [2048 x 1024 x 2048]
        if (i == NBLK-1) {
            mmagemm_k<2,0,0><<<dim3(D_MODEL/128, M_TOK/128), 256, GSM_TOTAL>>>(
                pA0, pA1, w0 + OFF_OUT, w1 + OFF_OUT, nullptr, out, nullptr, nullptr,
                M_TOK, D_MODEL, D_INNER, 0);
        } else {
            mmagemm_k<2,1,0><<<dim3(D_MODEL/128, M_TOK/128), 256, GSM_TOTAL>>>(
                pA0, pA1, w0 + OFF_OUT, w1 + OFF_OUT, nullptr, nullptr, pH0, pH1,
                M_TOK, D_MODEL, D_INNER, 0);
        }
    }
    (void)in_sizes; (void)n_in; (void)out_size;
}

// round 16
// speedup vs baseline: 1.4335x; 1.4335x over previous
#include <cuda_runtime.h>
#include <cuda_bf16.h>
#include <math.h>
#include <stdint.h>

#define D_MODEL 1024
#define D_STATE 16
#define D_CONV  4
#define D_INNER 2048
#define DT_RANK 64
#define NBLK    4
#define BATCH   2
#define SEQLEN  1024
#define M_TOK   (BATCH*SEQLEN)   // 2048 tokens
#define XD      96               // dt_rank + 2*d_state

// weight layout inside the big split buffers (elems, per layer)
#define WL_IN   (2*D_INNER*D_MODEL)
#define WL_XP   (128*D_INNER)
#define WL_DT   (D_INNER*DT_RANK)
#define WL_OUT  (D_MODEL*D_INNER)
#define OFF_XP  WL_IN
#define OFF_DT  (WL_IN + WL_XP)
#define OFF_OUT (WL_IN + WL_XP + WL_DT)
#define WPL     (WL_IN + WL_XP + WL_DT + WL_OUT)
#define WTOT    ((size_t)NBLK * WPL)

// ---------------- scratch (no allocation allowed) ----------------
__device__ __align__(256) float g_xz[(size_t)M_TOK*2*D_INNER];
__device__ __align__(256) float g_u[(size_t)M_TOK*D_INNER];
__device__ __align__(256) float g_xdbl[M_TOK*XD];
__device__ __align__(256) float g_part[(size_t)2*M_TOK*D_MODEL];  // 16MB (>= GEMM2's 8*M_TOK*128)
__device__ __align__(256) float g_dt[(size_t)M_TOK*D_INNER];
// bf16 split activation buffers (hi/lo)
__device__ __align__(256) __nv_bfloat16 g_A0[(size_t)M_TOK*D_INNER];
__device__ __align__(256) __nv_bfloat16 g_A1[(size_t)M_TOK*D_INNER];
__device__ __align__(256) __nv_bfloat16 g_H0[(size_t)M_TOK*D_MODEL];
__device__ __align__(256) __nv_bfloat16 g_H1[(size_t)M_TOK*D_MODEL];
// bf16 split weight buffers: ALL layers, ALL weight types
__device__ __align__(256) __nv_bfloat16 g_W0[WTOT];
__device__ __align__(256) __nv_bfloat16 g_W1[WTOT];

__device__ __forceinline__ float siluf(float v) {
    return v / (1.f + __expf(-v));
}

__device__ __forceinline__ uint32_t smem_u32(const void* p) {
    uint32_t a;
    asm("{ .reg .u64 t; cvta.to.shared.u64 t, %1; cvt.u32.u64 %0, t; }" : "=r"(a) : "l"(p));
    return a;
}
#define SWZ128(o) ((o) ^ (((o) >> 3) & 0x70))

// ---- cp.async helpers ----
__device__ __forceinline__ void cp16(uint32_t saddr, const void* gaddr) {
    asm volatile("cp.async.cg.shared.global [%0], [%1], 16;" :: "r"(saddr), "l"(gaddr));
}
__device__ __forceinline__ void cp_commit() { asm volatile("cp.async.commit_group;"); }
template<int N> __device__ __forceinline__ void cp_wait() {
    asm volatile("cp.async.wait_group %0;" :: "n"(N));
}

// ---- ldmatrix + mma.sync ----
__device__ __forceinline__ void ldm_x4(uint32_t addr, uint32_t f[4]) {
    asm volatile("ldmatrix.sync.aligned.m8n8.x4.shared.b16 {%0,%1,%2,%3}, [%4];"
                 : "=r"(f[0]), "=r"(f[1]), "=r"(f[2]), "=r"(f[3]) : "r"(addr));
}
__device__ __forceinline__ void mma16816(float c[4], const uint32_t a[4],
                                         uint32_t b0, uint32_t b1) {
    asm volatile(
        "mma.sync.aligned.m16n8k16.row.col.f32.bf16.bf16.f32 "
        "{%0,%1,%2,%3}, {%4,%5,%6,%7}, {%8,%9}, {%0,%1,%2,%3};"
        : "+f"(c[0]), "+f"(c[1]), "+f"(c[2]), "+f"(c[3])
        : "r"(a[0]), "r"(a[1]), "r"(a[2]), "r"(a[3]), "r"(b0), "r"(b1));
}

// ================= bf16x2-split HMMA GEMM (128x128 tile) =================
#define GSM_STAGE 65536
#define GSM_TOTAL (3*GSM_STAGE)

template<int EPI, int OSPLIT, int SPLITK>
__global__ void __launch_bounds__(256, 1) mmagemm_k(
    const __nv_bfloat16* __restrict__ A0, const __nv_bfloat16* __restrict__ A1,
    const __nv_bfloat16* __restrict__ W0, const __nv_bfloat16* __restrict__ W1,
    const float* __restrict__ bias, float* __restrict__ C,
    __nv_bfloat16* __restrict__ Chi, __nv_bfloat16* __restrict__ Clo,
    int M, int N, int K, int ksplit)
{
    extern __shared__ char dsm[];
    const uint32_t sb = smem_u32(dsm);
    const int tid  = threadIdx.x;
    const int wid  = tid >> 5;
    const int lane = tid & 31;
    const int wm = wid & 3;
    const int wn = wid >> 2;
    const int bm = blockIdx.y * 128;
    const int bn = blockIdx.x * 128;

    int kbase = 0, Kloc = K;
    if (SPLITK) {
        kbase = blockIdx.z * ksplit;
        Kloc  = ksplit;
        C += (size_t)blockIdx.z * (size_t)M * N;
    }

    const __nv_bfloat16* gb[4] = {
        A0 + (size_t)bm * K + kbase, A1 + (size_t)bm * K + kbase,
        W0 + (size_t)bn * K + kbase, W1 + (size_t)bn * K + kbase };

    const int ch = tid & 7;
    const int r0 = tid >> 3;

    auto issue_quarter = [&](int kt, int stage, int buf) {
        uint32_t st = sb + stage * GSM_STAGE + buf * 16384;
        const __nv_bfloat16* g = gb[buf] + kt + ch * 8;
#pragma unroll
        for (int j = 0; j < 4; j++) {
            int row = r0 + j * 32;
            uint32_t o = (uint32_t)(row * 128 + ch * 16);
            cp16(st + SWZ128(o), g + (size_t)row * K);
        }
    };

    float acc[2][8][4];
#pragma unroll
    for (int i = 0; i < 2; i++)
#pragma unroll
        for (int j = 0; j < 8; j++)
#pragma unroll
            for (int q = 0; q < 4; q++) acc[i][j][q] = 0.f;

    const int a_row = lane & 15;
    const int a_kof = (lane >> 4) << 3;
    const int b_row = (lane & 7) + ((lane & 16) ? 8 : 0);
    const int b_kof = (lane & 8) ? 8 : 0;

    const int T = Kloc / 64;
#pragma unroll
    for (int b = 0; b < 4; b++) issue_quarter(0, 0, b);
    cp_commit();
    if (T > 1) {
#pragma unroll
        for (int b = 0; b < 4; b++) issue_quarter(64, 1, b);
        cp_commit();
    }

    for (int t = 0; t < T; t++) {
        if (t + 1 < T) cp_wait<1>();
        else           cp_wait<0>();
        __syncthreads();

        const int s = t % 3;
        const uint32_t stA0 = sb + s * GSM_STAGE;
        const uint32_t stA1 = stA0 + 16384;
        const uint32_t stW0 = stA0 + 32768;
        const uint32_t stW1 = stA0 + 49152;

        const bool pf = (t + 2 < T);
        const int  ps = (t + 2) % 3;

#pragma unroll
        for (int kk = 0; kk < 4; kk++) {
            if (pf) issue_quarter((t + 2) * 64, ps, kk);
            const int k0 = kk * 16;
            uint32_t a0f[2][4], a1f[2][4];
#pragma unroll
            for (int mt = 0; mt < 2; mt++) {
                int row = wm * 32 + mt * 16 + a_row;
                uint32_t o = (uint32_t)(row * 128 + (k0 + a_kof) * 2);
                ldm_x4(stA0 + SWZ128(o), a0f[mt]);
                ldm_x4(stA1 + SWZ128(o), a1f[mt]);
            }
#pragma unroll
            for (int nq = 0; nq < 4; nq++) {
                int nrow = wn * 64 + nq * 16 + b_row;
                uint32_t o = (uint32_t)(nrow * 128 + (k0 + b_kof) * 2);
                uint32_t w0f[4], w1f[4];
                ldm_x4(stW0 + SWZ128(o), w0f);
                ldm_x4(stW1 + SWZ128(o), w1f);
#pragma unroll
                for (int mt = 0; mt < 2; mt++)
#pragma unroll
                    for (int h = 0; h < 2; h++) {
                        float* c = acc[mt][nq * 2 + h];
                        mma16816(c, a0f[mt], w0f[2*h], w0f[2*h+1]);
                        mma16816(c, a0f[mt], w1f[2*h], w1f[2*h+1]);
                        mma16816(c, a1f[mt], w0f[2*h], w0f[2*h+1]);
                    }
            }
        }
        if (pf) cp_commit();
    }

    const int erow = lane >> 2;
    const int ecol = (lane & 3) * 2;
#pragma unroll
    for (int mt = 0; mt < 2; mt++) {
#pragma unroll
        for (int nt = 0; nt < 8; nt++) {
            int n = bn + wn * 64 + nt * 8 + ecol;
#pragma unroll
            for (int h = 0; h < 2; h++) {
                int m = bm + wm * 32 + mt * 16 + erow + h * 8;
                float vx = acc[mt][nt][2*h], vy = acc[mt][nt][2*h+1];
                if (EPI == 1) {
                    vx += bias[n]; vy += bias[n+1];
                    vx = fmaxf(vx, 0.f) + log1pf(__expf(-fabsf(vx)));
                    vy = fmaxf(vy, 0.f) + log1pf(__expf(-fabsf(vy)));
                }
                if (EPI == 2) { vx = siluf(vx); vy = siluf(vy); }
                if (OSPLIT) {
                    __nv_bfloat16 hx = __float2bfloat16(vx);
                    __nv_bfloat16 hy = __float2bfloat16(vy);
                    __nv_bfloat162 hp; hp.x = hx; hp.y = hy;
                    __nv_bfloat162 lp;
                    lp.x = __float2bfloat16(vx - __bfloat162float(hx));
                    lp.y = __float2bfloat16(vy - __bfloat162float(hy));
                    *reinterpret_cast<__nv_bfloat162*>(Chi + (size_t)m * N + n) = hp;
                    *reinterpret_cast<__nv_bfloat162*>(Clo + (size_t)m * N + n) = lp;
                } else {
                    float2 v = {vx, vy};
                    *reinterpret_cast<float2*>(C + (size_t)m * N + n) = v;
                }
            }
        }
    }
}

// ================= 256x128-tile HMMA GEMM, split-K, raw fp32 partials =================
#define BSM_STAGE 98304            // A0 32K | A1 32K | W0 16K | W1 16K
#define BSM_TOTAL (2*BSM_STAGE)

__global__ void __launch_bounds__(256, 1) mmabig_k(
    const __nv_bfloat16* __restrict__ A0, const __nv_bfloat16* __restrict__ A1,
    const __nv_bfloat16* __restrict__ W0, const __nv_bfloat16* __restrict__ W1,
    float* __restrict__ C, int M, int N, int K, int ksplit)
{
    extern __shared__ char dsm[];
    const uint32_t sb = smem_u32(dsm);
    const int tid  = threadIdx.x;
    const int wid  = tid >> 5;
    const int lane = tid & 31;
    const int wm = wid & 3;          // 4 M-warps x 64 rows
    const int wn = wid >> 2;         // 2 N-warps x 64 cols
    const int bm = blockIdx.y * 256;
    const int bn = blockIdx.x * 128;
    const int kbase = blockIdx.z * ksplit;
    C += (size_t)blockIdx.z * (size_t)M * N;

    const __nv_bfloat16* gb[4] = {
        A0 + (size_t)bm * K + kbase, A1 + (size_t)bm * K + kbase,
        W0 + (size_t)bn * K + kbase, W1 + (size_t)bn * K + kbase };
    const uint32_t bufoff[4] = {0u, 32768u, 65536u, 81920u};

    const int ch = tid & 7;
    const int r0 = tid >> 3;

    auto issue_buf = [&](int kt, int stage, int buf) {
        uint32_t st = sb + stage * BSM_STAGE + bufoff[buf];
        const __nv_bfloat16* g = gb[buf] + kt + ch * 8;
        const int nj = (buf < 2) ? 8 : 4;    // A tiles: 256 rows, W tiles: 128
        for (int j = 0; j < nj; j++) {
            int row = r0 + j * 32;
            uint32_t o = (uint32_t)(row * 128 + ch * 16);
            cp16(st + SWZ128(o), g + (size_t)row * K);
        }
    };

    float acc[4][8][4];
#pragma unroll
    for (int i = 0; i < 4; i++)
#pragma unroll
        for (int j = 0; j < 8; j++)
#pragma unroll
            for (int q = 0; q < 4; q++) acc[i][j][q] = 0.f;

    const int a_row = lane & 15;
    const int a_kof = (lane >> 4) << 3;
    const int b_row = (lane & 7) + ((lane & 16) ? 8 : 0);
    const int b_kof = (lane & 8) ? 8 : 0;

    const int T = ksplit / 64;
#pragma unroll
    for (int b = 0; b < 4; b++) issue_buf(0, 0, b);
    cp_commit();

    for (int t = 0; t < T; t++) {
        cp_wait<0>();
        __syncthreads();

        const int s = t & 1;
        const uint32_t stA0 = sb + s * BSM_STAGE;
        const uint32_t stA1 = stA0 + 32768;
        const uint32_t stW0 = stA0 + 65536;
        const uint32_t stW1 = stA0 + 81920;
        const bool pf = (t + 1 < T);

#pragma unroll
        for (int kk = 0; kk < 4; kk++) {
            if (pf) issue_buf((t + 1) * 64, s ^ 1, kk);
            const int k0 = kk * 16;
            uint32_t a0f[4][4], a1f[4][4];
#pragma unroll
            for (int mt = 0; mt < 4; mt++) {
                int row = wm * 64 + mt * 16 + a_row;
                uint32_t o = (uint32_t)(row * 128 + (k0 + a_kof) * 2);
                ldm_x4(stA0 + SWZ128(o), a0f[mt]);
                ldm_x4(stA1 + SWZ128(o), a1f[mt]);
            }
#pragma unroll
            for (int nq = 0; nq < 4; nq++) {
                int nrow = wn * 64 + nq * 16 + b_row;
                uint32_t o = (uint32_t)(nrow * 128 + (k0 + b_kof) * 2);
                uint32_t w0f[4], w1f[4];
                ldm_x4(stW0 + SWZ128(o), w0f);
                ldm_x4(stW1 + SWZ128(o), w1f);
#pragma unroll
                for (int mt = 0; mt < 4; mt++)
#pragma unroll
                    for (int h = 0; h < 2; h++) {
                        float* c = acc[mt][nq * 2 + h];
                        mma16816(c, a0f[mt], w0f[2*h], w0f[2*h+1]);
                        mma16816(c, a0f[mt], w1f[2*h], w1f[2*h+1]);
                        mma16816(c, a1f[mt], w0f[2*h], w0f[2*h+1]);
                    }
            }
        }
        if (pf) cp_commit();
    }

    const int erow = lane >> 2;
    const int ecol = (lane & 3) * 2;
#pragma unroll
    for (int mt = 0; mt < 4; mt++) {
#pragma unroll
        for (int nt = 0; nt < 8; nt++) {
            int n = bn + wn * 64 + nt * 8 + ecol;
#pragma unroll
            for (int h = 0; h < 2; h++) {
                int m = bm + wm * 64 + mt * 16 + erow + h * 8;
                float2 v = {acc[mt][nt][2*h], acc[mt][nt][2*h+1]};
                *reinterpret_cast<float2*>(C + (size_t)m * N + n) = v;
            }
        }
    }
}

// ---- reduce 2 split-K partials + silu (+ optional bf16 split out) ----
template<int OSPLIT>
__global__ void reduce2_silu_k(const float* __restrict__ part, float* __restrict__ out,
                               __nv_bfloat16* __restrict__ hi, __nv_bfloat16* __restrict__ lo)
{
    int i = blockIdx.x * blockDim.x + threadIdx.x;   // < M_TOK*D_MODEL
    float v = siluf(part[i] + part[(size_t)M_TOK*D_MODEL + i]);
    if (OSPLIT) {
        __nv_bfloat16 h = __float2bfloat16(v);
        hi[i] = h;
        lo[i] = __float2bfloat16(v - __bfloat162float(h));
    } else {
        out[i] = v;
    }
}

// ======== mega weight cvt ========
__global__ void cvt_all_k(const float* __restrict__ inw, const float* __restrict__ xpw,
                          const float* __restrict__ dtw, const float* __restrict__ outw,
                          __nv_bfloat16* __restrict__ hi, __nv_bfloat16* __restrict__ lo)
{
    size_t i = (size_t)blockIdx.x * blockDim.x + threadIdx.x;
    int layer = (int)(i / WPL);
    int r = (int)(i - (size_t)layer * WPL);
    float v;
    if (r < WL_IN) {
        v = inw[(size_t)layer * WL_IN + r];
    } else if (r < OFF_DT) {
        int rr = r - OFF_XP;
        int row = rr / D_INNER, col = rr - row * D_INNER;
        v = (row < XD) ? xpw[(size_t)layer * XD * D_INNER + (size_t)row * D_INNER + col] : 0.f;
    } else if (r < OFF_OUT) {
        v = dtw[(size_t)layer * WL_DT + (r - OFF_DT)];
    } else {
        v = outw[(size_t)layer * WL_OUT + (r - OFF_OUT)];
    }
    __nv_bfloat16 h = __float2bfloat16(v);
    hi[i] = h;
    lo[i] = __float2bfloat16(v - __bfloat162float(h));
}

// ================= embedding (split out) =================
__global__ void embed_split_k(const float* __restrict__ x, const float* __restrict__ ew,
                              const float* __restrict__ eb,
                              __nv_bfloat16* __restrict__ hi,
                              __nv_bfloat16* __restrict__ lo)
{
    int i = blockIdx.x * blockDim.x + threadIdx.x;
    int d = i % D_MODEL, m = i / D_MODEL;
    float v = fmaf(x[m], ew[d], eb[d]);
    __nv_bfloat16 h = __float2bfloat16(v);
    hi[i] = h;
    lo[i] = __float2bfloat16(v - __bfloat162float(h));
}

// ============ causal depthwise conv + silu (fp32 + split) ============
__global__ void conv_silu_k(const float* __restrict__ xz, const float* __restrict__ cw,
                            const float* __restrict__ cb, float* __restrict__ u,
                            __nv_bfloat16* __restrict__ uhi, __nv_bfloat16* __restrict__ ulo)
{
    int i = blockIdx.x * blockDim.x + threadIdx.x;
    int d = i % D_INNER;
    int m = i / D_INNER;
    int t = m % SEQLEN;
    float acc = cb[d];
#pragma unroll
    for (int k = 0; k < D_CONV; k++) {
        int tt = t - (D_CONV-1) + k;
        if (tt >= 0)
            acc = fmaf(cw[d*D_CONV + k], xz[(size_t)(m-(D_CONV-1)+k)*(2*D_INNER) + d], acc);
    }
    float v = siluf(acc);
    u[i] = v;
    __nv_bfloat16 h = __float2bfloat16(v);
    uhi[i] = h;
    ulo[i] = __float2bfloat16(v - __bfloat162float(h));
}

// ======= reduce 8 split-K partials -> xdbl fp32 + dt_lo bf16 split =======
__global__ void reduce8_k(const float* __restrict__ part,
                          float* __restrict__ xdbl,
                          __nv_bfloat16* __restrict__ dh, __nv_bfloat16* __restrict__ dl)
{
    int i = blockIdx.x * blockDim.x + threadIdx.x;
    if (i < M_TOK * XD) {
        int m = i / XD, c = i - m * XD;
        float s = 0.f;
#pragma unroll
        for (int z = 0; z < 8; z++)
            s += part[(size_t)z * M_TOK * 128 + (size_t)m * 128 + c];
        xdbl[i] = s;
        if (c < DT_RANK) {
            __nv_bfloat16 h = __float2bfloat16(s);
            dh[(size_t)m * DT_RANK + c] = h;
            dl[(size_t)m * DT_RANK + c] = __float2bfloat16(s - __bfloat162float(h));
        }
    }
}

// ========= selective scan: shfl-free (deferred smem reduction) =========
// 512 threads: compute phase thread=(dl,n) over 32 d x 16 states;
// reduce phase thread=(tl,dd) over 16 steps x 32 d. 17-padded s_p kills conflicts.
#define SC_D 32
#define SC_T 16
__global__ void __launch_bounds__(512) scan_k(
    const float* __restrict__ dt, const float* __restrict__ u,
    const float* __restrict__ xdbl, const float* __restrict__ xz,
    const float* __restrict__ A_log, const float* __restrict__ Dp,
    __nv_bfloat16* __restrict__ yhi, __nv_bfloat16* __restrict__ ylo)
{
    __shared__ float s_dt[SC_T][SC_D];
    __shared__ float s_u [SC_T][SC_D];
    __shared__ float s_z [SC_T][SC_D];
    __shared__ float s_B [SC_T][D_STATE];
    __shared__ float s_C [SC_T][D_STATE];
    __shared__ float s_p [SC_T][SC_D][17];

    const int b  = blockIdx.y;
    const int d0 = blockIdx.x * SC_D;
    const int tid = threadIdx.x;
    const int n  = tid & 15;          // compute-phase state
    const int dl = tid >> 4;          // compute-phase d (0..31)
    const int stl = tid >> 5;         // staging/reduce-phase step (0..15)
    const int sdd = tid & 31;         // staging/reduce-phase d (0..31)

    const float Aval = -__expf(A_log[(d0 + dl)*D_STATE + n]);
    const float Dval = Dp[d0 + sdd];
    float s = 0.f;
    const size_t rowbase = (size_t)b * SEQLEN;

    for (int t0 = 0; t0 < SEQLEN; t0 += SC_T) {
        // stage inputs (coalesced: consecutive tid -> consecutive d)
        {
            size_t r = rowbase + t0 + stl;
            s_dt[stl][sdd] = dt[r*D_INNER + d0 + sdd];
            s_u [stl][sdd] = u [r*D_INNER + d0 + sdd];
            s_z [stl][sdd] = xz[r*(2*D_INNER) + D_INNER + d0 + sdd];
        }
        if (tid < SC_T*D_STATE) {
            int tl2 = tid >> 4, nn = tid & 15;
            size_t r2 = rowbase + t0 + tl2;
            s_B[tl2][nn] = xdbl[r2*XD + DT_RANK + nn];
            s_C[tl2][nn] = xdbl[r2*XD + DT_RANK + D_STATE + nn];
        }
        __syncthreads();

        // recurrence: critical path is ONE fma per step (dA/b computed off-chain)
#pragma unroll
        for (int tl = 0; tl < SC_T; tl++) {
            float dtv = s_dt[tl][dl];
            float dA  = __expf(dtv * Aval);
            s = fmaf(dA, s, dtv * s_u[tl][dl] * s_B[tl][n]);
            s_p[tl][dl][n] = s * s_C[tl][n];
        }
        __syncthreads();

        // deferred reduction over the 16 states + gating + split write
        {
            float y = 0.f;
#pragma unroll
            for (int nn = 0; nn < 16; nn++) y += s_p[stl][sdd][nn];
            float uv = s_u[stl][sdd];
            float v  = fmaf(Dval, uv, y) * siluf(s_z[stl][sdd]);
            __nv_bfloat16 h = __float2bfloat16(v);
            size_t o = (rowbase + t0 + stl)*D_INNER + d0 + sdd;
            yhi[o] = h;
            ylo[o] = __float2bfloat16(v - __bfloat162float(h));
        }
        __syncthreads();
    }
}

// ---------------- host ----------------
extern "C" void kernel_launch(void* const* d_in, const int* in_sizes, int n_in,
                              void* d_out, int out_size)
{
    const float* x          = (const float*)d_in[0];
    const float* emb_w      = (const float*)d_in[1];
    const float* emb_b      = (const float*)d_in[2];
    const float* in_proj_w  = (const float*)d_in[3];
    const float* conv_w     = (const float*)d_in[4];
    const float* conv_b     = (const float*)d_in[5];
    const float* x_proj_w   = (const float*)d_in[6];
    const float* dt_proj_w  = (const float*)d_in[7];
    const float* dt_proj_b  = (const float*)d_in[8];
    const float* A_log      = (const float*)d_in[9];
    const float* D_param    = (const float*)d_in[10];
    const float* out_proj_w = (const float*)d_in[11];
    float* out = (float*)d_out;

    float *pxz, *pu, *pxdbl, *ppart, *pdt;
    __nv_bfloat16 *pA0, *pA1, *pH0, *pH1, *pW0, *pW1;
    cudaGetSymbolAddress((void**)&pxz,   g_xz);
    cudaGetSymbolAddress((void**)&pu,    g_u);
    cudaGetSymbolAddress((void**)&pxdbl, g_xdbl);
    cudaGetSymbolAddress((void**)&ppart, g_part);
    cudaGetSymbolAddress((void**)&pdt,   g_dt);
    cudaGetSymbolAddress((void**)&pA0,   g_A0);
    cudaGetSymbolAddress((void**)&pA1,   g_A1);
    cudaGetSymbolAddress((void**)&pH0,   g_H0);
    cudaGetSymbolAddress((void**)&pH1,   g_H1);
    cudaGetSymbolAddress((void**)&pW0,   g_W0);
    cudaGetSymbolAddress((void**)&pW1,   g_W1);

    cudaFuncSetAttribute(mmagemm_k<0,0,0>, cudaFuncAttributeMaxDynamicSharedMemorySize, GSM_TOTAL);
    cudaFuncSetAttribute(mmagemm_k<0,0,1>, cudaFuncAttributeMaxDynamicSharedMemorySize, GSM_TOTAL);
    cudaFuncSetAttribute(mmagemm_k<1,0,0>, cudaFuncAttributeMaxDynamicSharedMemorySize, GSM_TOTAL);
    cudaFuncSetAttribute(mmabig_k, cudaFuncAttributeMaxDynamicSharedMemorySize, BSM_TOTAL);

    // all weight conversions in one launch
    cvt_all_k<<<(unsigned)(WTOT/256), 256>>>(in_proj_w, x_proj_w, dt_proj_w, out_proj_w, pW0, pW1);

    embed_split_k<<<(M_TOK*D_MODEL)/256, 256>>>(x, emb_w, emb_b, pH0, pH1);

    for (int i = 0; i < NBLK; i++) {
        const __nv_bfloat16* w0 = pW0 + (size_t)i * WPL;
        const __nv_bfloat16* w1 = pW1 + (size_t)i * WPL;

        // --- GEMM1 (HMMA): xz = h @ in_proj_w^T  [2048 x 4096 x 1024]
        mmagemm_k<0,0,0><<<dim3((2*D_INNER)/128, M_TOK/128), 256, GSM_TOTAL>>>(
            pH0, pH1, w0, w1, nullptr, pxz, nullptr, nullptr,
            M_TOK, 2*D_INNER, D_MODEL, 0);

        // --- depthwise conv + silu -> u (fp32 + split)
        conv_silu_k<<<(M_TOK*D_INNER)/256, 256>>>(
            pxz, conv_w + (size_t)i*D_INNER*D_CONV, conv_b + (size_t)i*D_INNER,
            pu, pA0, pA1);

        // --- GEMM2 (HMMA split-K x8): x_dbl = u @ x_proj_w^T  [2048 x 96(pad128) x 2048]
        mmagemm_k<0,0,1><<<dim3(1, M_TOK/128, 8), 256, GSM_TOTAL>>>(
            pA0, pA1, w0 + OFF_XP, w1 + OFF_XP, nullptr, ppart, nullptr, nullptr,
            M_TOK, 128, D_INNER, D_INNER/8);
        reduce8_k<<<(M_TOK*XD + 255)/256, 256>>>(ppart, pxdbl, pA0, pA1);

        // --- GEMM3 (HMMA): dt = softplus(dt_lo @ dt_proj_w^T + b)  [2048 x 2048 x 64]
        mmagemm_k<1,0,0><<<dim3(D_INNER/128, M_TOK/128), 256, GSM_TOTAL>>>(
            pA0, pA1, w0 + OFF_DT, w1 + OFF_DT, dt_proj_b + (size_t)i*D_INNER,
            pdt, nullptr, nullptr, M_TOK, D_INNER, DT_RANK, 0);

        // --- selective scan + gating -> yg split (shfl-free)
        scan_k<<<dim3(D_INNER/SC_D, BATCH), 512>>>(
            pdt, pu, pxdbl, pxz,
            A_log + (size_t)i*D_INNER*D_STATE, D_param + (size_t)i*D_INNER, pA0, pA1);

        // --- GEMM4 (256x128 tile, split-K x2): h' = silu(yg @ out_proj_w^T)
        mmabig_k<<<dim3(D_MODEL/128, M_TOK/256, 2), 256, BSM_TOTAL>>>(
            pA0, pA1, w0 + OFF_OUT, w1 + OFF_OUT, ppart,
            M_TOK, D_MODEL, D_INNER, D_INNER/2);
        if (i == NBLK-1) {
            reduce2_silu_k<0><<<(M_TOK*D_MODEL)/256, 256>>>(ppart, out, nullptr, nullptr);
        } else {
            reduce2_silu_k<1><<<(M_TOK*D_MODEL)/256, 256>>>(ppart, nullptr, pH0, pH1);
        }
    }
    (void)in_sizes; (void)n_in; (void)out_size;
}